// round 14
// baseline (speedup 1.0000x reference)
#include <cuda_runtime.h>
#include <cuda_bf16.h>
#include <math.h>
#include <stdint.h>

// Problem constants
#define BB     8
#define SS     2048
#define CC     8
#define DD     9
#define WIN    60
#define NTOT   (BB * SS)      // 16384
#define SIGCH  285
#define KP1    288            // padded K for GEMM1 (9 chunks of 32)
#define H2C    512
#define H1C    256
#define NW     8

// ---------------- scratch ----------------
__device__ __nv_bfloat16 g_fhi[(size_t)NTOT * KP1];
__device__ __nv_bfloat16 g_flo[(size_t)NTOT * KP1];
__device__ __nv_bfloat16 g_hhi[(size_t)NTOT * H2C];
__device__ __nv_bfloat16 g_hlo[(size_t)NTOT * H2C];
__device__ __nv_bfloat16 g_w1hi[KP1 * H2C];
__device__ __nv_bfloat16 g_w1lo[KP1 * H2C];
__device__ __nv_bfloat16 g_w2hi[H2C * H1C];
__device__ __nv_bfloat16 g_w2lo[H2C * H1C];

// ---------------- Lyndon tables ----------------
struct LyndonTab { short l2[36]; short l3[240]; };
constexpr LyndonTab make_tab() {
    LyndonTab t{};
    int n2 = 0, n3 = 0;
    for (int i = 0; i < DD; i++)
        for (int j = 0; j < DD; j++)
            if (i < j) t.l2[n2++] = (short)(i * 9 + j);
    for (int i = 0; i < DD; i++)
        for (int j = 0; j < DD; j++)
            for (int k = 0; k < DD; k++) {
                int e  = (i * 9 + j) * 9 + k;
                int r1 = (j * 9 + k) * 9 + i;
                int r2 = (k * 9 + i) * 9 + j;
                if (e < r1 && e < r2) t.l3[n3++] = (short)e;
            }
    return t;
}
__constant__ LyndonTab c_tab = make_tab();

// ---------------- helpers ----------------
__device__ __forceinline__ float gelu_exact(float v) {
    return 0.5f * v * (1.0f + erff(v * 0.70710678118654752f));
}
__device__ __forceinline__ void feat_store(int n, int idx, float v) {
    __nv_bfloat16 h = __float2bfloat16(v);
    g_fhi[(size_t)n * KP1 + idx] = h;
    g_flo[(size_t)n * KP1 + idx] = __float2bfloat16(v - __bfloat162float(h));
}
__device__ __forceinline__ uint32_t pkbf2(float a, float b) {
    __nv_bfloat162 t = __floats2bfloat162_rn(a, b);
    return *(uint32_t*)&t;
}
__device__ __forceinline__ uint32_t smem_u32(const void* p) {
    uint32_t a;
    asm("{ .reg .u64 t; cvta.to.shared.u64 t, %1; cvt.u32.u64 %0, t; }" : "=r"(a) : "l"(p));
    return a;
}
__device__ __forceinline__ void ldmx4(uint32_t* r, uint32_t addr) {
    asm volatile("ldmatrix.sync.aligned.m8n8.x4.shared.b16 {%0,%1,%2,%3}, [%4];"
                 : "=r"(r[0]), "=r"(r[1]), "=r"(r[2]), "=r"(r[3]) : "r"(addr));
}
__device__ __forceinline__ void ldmx4t(uint32_t* r, uint32_t addr) {
    asm volatile("ldmatrix.sync.aligned.m8n8.x4.trans.shared.b16 {%0,%1,%2,%3}, [%4];"
                 : "=r"(r[0]), "=r"(r[1]), "=r"(r[2]), "=r"(r[3]) : "r"(addr));
}
__device__ __forceinline__ void mma16816(float* d, const uint32_t* a,
                                         uint32_t b0, uint32_t b1) {
    asm volatile("mma.sync.aligned.m16n8k16.row.col.f32.bf16.bf16.f32 "
                 "{%0,%1,%2,%3}, {%4,%5,%6,%7}, {%8,%9}, {%0,%1,%2,%3};"
                 : "+f"(d[0]), "+f"(d[1]), "+f"(d[2]), "+f"(d[3])
                 : "r"(a[0]), "r"(a[1]), "r"(a[2]), "r"(a[3]), "r"(b0), "r"(b1));
}
__device__ __forceinline__ void cpa16(uint32_t dst, const void* src) {
    asm volatile("cp.async.cg.shared.global [%0], [%1], 16;" :: "r"(dst), "l"(src));
}
__device__ __forceinline__ void cpa_commit() {
    asm volatile("cp.async.commit_group;" ::: "memory");
}
template <int N>
__device__ __forceinline__ void cpa_wait() {
    asm volatile("cp.async.wait_group %0;" :: "n"(N) : "memory");
}
// ---- packed fp32x2 (FFMA2) ----
__device__ __forceinline__ unsigned long long pk2f(float lo, float hi) {
    unsigned long long r;
    asm("mov.b64 %0, {%1, %2};" : "=l"(r) : "f"(lo), "f"(hi));
    return r;
}
__device__ __forceinline__ void upk2f(unsigned long long v, float& lo, float& hi) {
    asm("mov.b64 {%0, %1}, %2;" : "=f"(lo), "=f"(hi) : "l"(v));
}
__device__ __forceinline__ void ffma2(unsigned long long& d, unsigned long long a,
                                      unsigned long long b) {
    asm("fma.rn.f32x2 %0, %1, %2, %0;" : "+l"(d) : "l"(a), "l"(b));
}

// ---------------------------------------------------------------------------
// Prep: bf16 hi/lo weights in natural [K][N] layout (K padded for w1).
// ---------------------------------------------------------------------------
__global__ void prep_kernel(const float* __restrict__ w1, const float* __restrict__ w2) {
    int idx = blockIdx.x * 256 + threadIdx.x;
    if (idx < KP1 * H2C) {
        int k = idx / H2C, n = idx - k * H2C;
        float v = (k < SIGCH) ? w1[(size_t)k * H2C + n] : 0.0f;
        __nv_bfloat16 h = __float2bfloat16(v);
        g_w1hi[idx] = h;
        g_w1lo[idx] = __float2bfloat16(v - __bfloat162float(h));
    } else {
        int j = idx - KP1 * H2C;
        if (j < H2C * H1C) {
            float v = w2[j];
            __nv_bfloat16 h = __float2bfloat16(v);
            g_w2hi[j] = h;
            g_w2lo[j] = __float2bfloat16(v - __bfloat162float(h));
        }
    }
}

// ---------------------------------------------------------------------------
// Kernel A: log-signature features (warp per window) -> bf16 hi/lo [n][288]
// Chen scan with S3 rows packed as f32x2 (FFMA2): 15 packed FMAs replace 27
// scalar FMAs per step per lane.
// ---------------------------------------------------------------------------
__global__ __launch_bounds__(256) void sig_kernel(const float* __restrict__ x) {
    __shared__ float vs3[NW][732];
    __shared__ float s2s[NW][81];
    __shared__ float s1s[NW][12];

    const int w    = threadIdx.x >> 5;
    const int lane = threadIdx.x & 31;
    const int n    = blockIdx.x * NW + w;
    const int bb   = n >> 11;
    const int ss   = n & 2047;

    float* vbuf = vs3[w];
    const float inv59 = 1.0f / 59.0f;

    for (int step = lane; step < WIN; step += 32) {
        int pos  = ss + step - (WIN - 1);
        int posc = pos < 0 ? 0 : pos;
        const float* xr = x + ((size_t)bb * SS + posc) * CC;
        float4 a0 = *(const float4*)(xr);
        float4 a1 = *(const float4*)(xr + 4);
        float vt;
        float4 d0, d1;
        if (step == 0) {
            vt = 0.0f;
            d0 = a0; d1 = a1;
        } else {
            vt = inv59;
            int pm  = pos - 1;
            int pmc = pm < 0 ? 0 : pm;
            const float* xp = x + ((size_t)bb * SS + pmc) * CC;
            float4 b0 = *(const float4*)(xp);
            float4 b1 = *(const float4*)(xp + 4);
            d0.x = a0.x - b0.x; d0.y = a0.y - b0.y; d0.z = a0.z - b0.z; d0.w = a0.w - b0.w;
            d1.x = a1.x - b1.x; d1.y = a1.y - b1.y; d1.z = a1.z - b1.z; d1.w = a1.w - b1.w;
        }
        float* vv = vbuf + step * 12;
        vv[0] = vt;
        vv[1] = d0.x; vv[2] = d0.y; vv[3] = d0.z; vv[4] = d0.w;
        vv[5] = d1.x; vv[6] = d1.y; vv[7] = d1.z; vv[8] = d1.w;
    }
    __syncwarp();

    unsigned long long S3p[3][5];     // packed pairs: (0,1)(2,3)(4,5)(6,7)(8,pad)
    float S2r[3];
    float s1i = 0.0f;
    const int li = lane / 3;
    const int jb = (lane % 3) * 3;

    if (lane < 27) {
#pragma unroll
        for (int c = 0; c < 3; c++) {
            S2r[c] = 0.0f;
#pragma unroll
            for (int q = 0; q < 5; q++) S3p[c][q] = 0ull;
        }
#pragma unroll 2
        for (int step = 0; step < WIN; step++) {
            const float* vv = vbuf + step * 12;
            float4 va = *(const float4*)(vv);
            float4 vb = *(const float4*)(vv + 4);
            float  v8 = vv[8];
            float  vi = vv[li];
            unsigned long long pv[5];
            pv[0] = pk2f(va.x, va.y);
            pv[1] = pk2f(va.z, va.w);
            pv[2] = pk2f(vb.x, vb.y);
            pv[3] = pk2f(vb.z, vb.w);
            pv[4] = pk2f(v8, 0.0f);
            float bcoef = fmaf(vi, 1.0f / 6.0f, 0.5f * s1i);
            float ccoef = fmaf(vi, 0.5f, s1i);
#pragma unroll
            for (int c = 0; c < 3; c++) {
                float vj = vv[jb + c];
                float a = fmaf(bcoef, vj, S2r[c]);
                unsigned long long pa = pk2f(a, a);
#pragma unroll
                for (int q = 0; q < 5; q++) ffma2(S3p[c][q], pv[q], pa);
                S2r[c] = fmaf(ccoef, vj, S2r[c]);
            }
            s1i += vi;
        }
    }
    __syncwarp();

    if (lane < 27) {
#pragma unroll
        for (int c = 0; c < 3; c++) {
            int p = li * 9 + jb + c;
            s2s[w][p] = S2r[c];
            float lo, hi;
#pragma unroll
            for (int q = 0; q < 4; q++) {
                upk2f(S3p[c][q], lo, hi);
                vs3[w][p * 9 + 2 * q]     = lo;
                vs3[w][p * 9 + 2 * q + 1] = hi;
            }
            upk2f(S3p[c][4], lo, hi);
            vs3[w][p * 9 + 8] = lo;
        }
        if ((lane % 3) == 0) s1s[w][li] = s1i;
    }
    __syncwarp();

    const float* S3s = vs3[w];
    const float* S2p = s2s[w];
    const float* S1p = s1s[w];

    if (lane < 9) feat_store(n, lane, S1p[lane]);

    for (int t = lane; t < 36; t += 32) {
        int e = c_tab.l2[t];
        int i = e / 9, j = e % 9;
        feat_store(n, 9 + t, S2p[e] - 0.5f * S1p[i] * S1p[j]);
    }
    for (int t = lane; t < 240; t += 32) {
        int e  = c_tab.l3[t];
        int k  = e % 9;
        int ij = e / 9;
        int j  = ij % 9;
        int i  = ij / 9;
        float v = S3s[e]
                - 0.5f * (S1p[i] * S2p[j * 9 + k] + S2p[ij] * S1p[k])
                + S1p[i] * S1p[j] * S1p[k] * (1.0f / 3.0f);
        feat_store(n, 45 + t, v);
    }
    for (int t = SIGCH + lane; t < KP1; t += 32) {
        g_fhi[(size_t)n * KP1 + t] = __float2bfloat16(0.0f);
        g_flo[(size_t)n * KP1 + t] = __float2bfloat16(0.0f);
    }
}

// ---------------------------------------------------------------------------
// GEMM1: D[64,512] = feats @ w1 ; GELU + LN ; h -> bf16 hi/lo.
// 256 CTAs x 512 thr (16 warps, 2x8). Warp tile 32x64. K = 9 chunks of 32.
// Double-buffered cp.async pipeline.
// ---------------------------------------------------------------------------
#define G1_AS    40              // A smem stride (halves)
#define G1_BS    520             // B smem stride (halves)
#define G1_A_HI  0
#define G1_A_LO  (G1_A_HI + 64 * G1_AS * 2)       // 5120
#define G1_B_HI  (G1_A_LO + 64 * G1_AS * 2)       // 10240
#define G1_B_LO  (G1_B_HI + 32 * G1_BS * 2)       // 43520
#define G1_BUFSZ (G1_B_LO + 32 * G1_BS * 2)       // 76800
#define G1_B1S   (2 * G1_BUFSZ)                   // 153600
#define G1_LNG   (G1_B1S + 2048)
#define G1_LNB   (G1_LNG + 2048)
#define G1_RS    (G1_LNB + 2048)
#define G1_RQ    (G1_RS + 2048)
#define G1_MU    (G1_RQ + 2048)
#define G1_RSD   (G1_MU + 256)
#define SMEM_G1  (G1_RSD + 256)

__device__ __forceinline__ void g1_stage(uint32_t sbuf, int row0, int ch, int tid) {
    {
        int arr = tid >> 8, idx = tid & 255;
        int r = idx >> 2, q = idx & 3;
        const __nv_bfloat16* src = arr ? g_flo : g_fhi;
        cpa16(sbuf + (arr ? G1_A_LO : G1_A_HI) + (uint32_t)(r * G1_AS + q * 8) * 2,
              (const char*)src + ((size_t)(row0 + r) * KP1 + ch * 32 + q * 8) * 2);
    }
#pragma unroll
    for (int it = tid; it < 4096; it += 512) {
        int arr = it >> 11, idx = it & 2047;
        int r = idx >> 6, c = idx & 63;
        const __nv_bfloat16* src = arr ? g_w1lo : g_w1hi;
        cpa16(sbuf + (arr ? G1_B_LO : G1_B_HI) + (uint32_t)(r * G1_BS + c * 8) * 2,
              (const char*)src + ((size_t)(ch * 32 + r) * H2C + c * 8) * 2);
    }
}

__global__ __launch_bounds__(512, 1) void gemm1_kernel(
    const float* __restrict__ b1, const float* __restrict__ lng,
    const float* __restrict__ lnb)
{
    extern __shared__ char smem[];
    const uint32_t sb = smem_u32(smem);
    const int tid  = threadIdx.x;
    const int lane = tid & 31;
    const int wid  = tid >> 5;
    const int wm   = wid >> 3;        // 0..1
    const int wn   = wid & 7;         // 0..7
    const int row0 = blockIdx.x * 64;

    float* b1s  = (float*)(smem + G1_B1S);
    float* lngs = (float*)(smem + G1_LNG);
    float* lnbs = (float*)(smem + G1_LNB);
    float* reds = (float*)(smem + G1_RS);   // [64][8]
    float* redq = (float*)(smem + G1_RQ);
    float* mus  = (float*)(smem + G1_MU);
    float* rsd  = (float*)(smem + G1_RSD);
    for (int i = tid; i < H2C; i += 512) {
        b1s[i] = b1[i]; lngs[i] = lng[i]; lnbs[i] = lnb[i];
    }

    const int mi = lane >> 3, ri = lane & 7;
    const uint32_t aA = ((uint32_t)((wm * 32 + ri + ((mi & 1) << 3)) * G1_AS
                                    + ((mi >> 1) << 3))) * 2;
    const uint32_t aB = ((uint32_t)((ri + ((mi & 1) << 3)) * G1_BS
                                    + wn * 64 + ((mi >> 1) << 3))) * 2;

    float acc[2][8][4];
#pragma unroll
    for (int m = 0; m < 2; m++)
#pragma unroll
        for (int n = 0; n < 8; n++)
#pragma unroll
            for (int e = 0; e < 4; e++) acc[m][n][e] = 0.0f;

    g1_stage(sb, row0, 0, tid);
    cpa_commit();

    for (int ch = 0; ch < 9; ch++) {
        if (ch + 1 < 9) {
            g1_stage(sb + ((ch + 1) & 1) * G1_BUFSZ, row0, ch + 1, tid);
            cpa_commit();
            cpa_wait<1>();
        } else {
            cpa_wait<0>();
        }
        __syncthreads();

        const uint32_t base = sb + (ch & 1) * G1_BUFSZ;
#pragma unroll
        for (int ks = 0; ks < 2; ks++) {
            uint32_t ah[2][4], al[2][4];
#pragma unroll
            for (int ma = 0; ma < 2; ma++) {
                uint32_t off = aA + (ma * 16 * G1_AS + ks * 16) * 2;
                ldmx4(ah[ma], base + G1_A_HI + off);
                ldmx4(al[ma], base + G1_A_LO + off);
            }
#pragma unroll
            for (int pn = 0; pn < 4; pn++) {
                uint32_t bh[4], bl[4];
                uint32_t off = aB + (ks * 16 * G1_BS + pn * 16) * 2;
                ldmx4t(bh, base + G1_B_HI + off);
                ldmx4t(bl, base + G1_B_LO + off);
#pragma unroll
                for (int ma = 0; ma < 2; ma++) {
#pragma unroll
                    for (int nn = 0; nn < 2; nn++) {
                        float* d = acc[ma][pn * 2 + nn];
                        mma16816(d, ah[ma], bh[nn * 2], bh[nn * 2 + 1]);
                        mma16816(d, al[ma], bh[nn * 2], bh[nn * 2 + 1]);
                        mma16816(d, ah[ma], bl[nn * 2], bl[nn * 2 + 1]);
                    }
                }
            }
        }
        __syncthreads();
    }

    // ---- Epilogue: bias + GELU in regs, LN stats ----
    float s1v[2][2] = {{0.f, 0.f}, {0.f, 0.f}};
    float s2v[2][2] = {{0.f, 0.f}, {0.f, 0.f}};
#pragma unroll
    for (int ma = 0; ma < 2; ma++)
#pragma unroll
        for (int na = 0; na < 8; na++) {
            int col = wn * 64 + na * 8 + (lane & 3) * 2;
#pragma unroll
            for (int e = 0; e < 4; e++) {
                float v = gelu_exact(acc[ma][na][e] + b1s[col + (e & 1)]);
                acc[ma][na][e] = v;
                s1v[ma][e >> 1] += v;
                s2v[ma][e >> 1] = fmaf(v, v, s2v[ma][e >> 1]);
            }
        }
#pragma unroll
    for (int off = 1; off <= 2; off <<= 1) {
#pragma unroll
        for (int ma = 0; ma < 2; ma++)
#pragma unroll
            for (int h = 0; h < 2; h++) {
                s1v[ma][h] += __shfl_xor_sync(0xffffffffu, s1v[ma][h], off);
                s2v[ma][h] += __shfl_xor_sync(0xffffffffu, s2v[ma][h], off);
            }
    }
    if ((lane & 3) == 0) {
#pragma unroll
        for (int ma = 0; ma < 2; ma++)
#pragma unroll
            for (int h = 0; h < 2; h++) {
                int row = wm * 32 + ma * 16 + h * 8 + (lane >> 2);
                reds[row * 8 + wn] = s1v[ma][h];
                redq[row * 8 + wn] = s2v[ma][h];
            }
    }
    __syncthreads();
    if (tid < 64) {
        float s = 0.f, q = 0.f;
#pragma unroll
        for (int w = 0; w < 8; w++) { s += reds[tid * 8 + w]; q += redq[tid * 8 + w]; }
        float mu  = s * (1.0f / 512.0f);
        float var = q * (1.0f / 512.0f) - mu * mu;
        mus[tid] = mu;
        rsd[tid] = rsqrtf(var + 1e-5f);
    }
    __syncthreads();

#pragma unroll
    for (int ma = 0; ma < 2; ma++)
#pragma unroll
        for (int h = 0; h < 2; h++) {
            int row = wm * 32 + ma * 16 + h * 8 + (lane >> 2);
            float mu = mus[row], rs = rsd[row];
            size_t gro = (size_t)(row0 + row) * H2C;
#pragma unroll
            for (int na = 0; na < 8; na++) {
                int col = wn * 64 + na * 8 + (lane & 3) * 2;
                float y0 = fmaf((acc[ma][na][h * 2]     - mu) * rs, lngs[col],     lnbs[col]);
                float y1 = fmaf((acc[ma][na][h * 2 + 1] - mu) * rs, lngs[col + 1], lnbs[col + 1]);
                __nv_bfloat16 h0 = __float2bfloat16(y0), h1 = __float2bfloat16(y1);
                float f0 = __bfloat162float(h0), f1 = __bfloat162float(h1);
                *(uint32_t*)((char*)g_hhi + (gro + col) * 2) = pkbf2(f0, f1);
                *(uint32_t*)((char*)g_hlo + (gro + col) * 2) = pkbf2(y0 - f0, y1 - f1);
            }
        }
}

// ---------------------------------------------------------------------------
// GEMM2: out[64,256] = h @ w2 + b2. 256 CTAs x 256 thr (8 warps, 2x4).
// Warp tile 32x64. K = 16 chunks of 32. Double-buffered cp.async pipeline.
// ---------------------------------------------------------------------------
#define G2_AS    40
#define G2_BS    264
#define G2_A_HI  0
#define G2_A_LO  (G2_A_HI + 64 * G2_AS * 2)       // 5120
#define G2_B_HI  (G2_A_LO + 64 * G2_AS * 2)       // 10240
#define G2_B_LO  (G2_B_HI + 32 * G2_BS * 2)       // 27136
#define G2_BUFSZ (G2_B_LO + 32 * G2_BS * 2)       // 44032
#define G2_B2S   (2 * G2_BUFSZ)                   // 88064
#define SMEM_G2  (G2_B2S + 1024)

__device__ __forceinline__ void g2_stage(uint32_t sbuf, int row0, int ch, int tid) {
#pragma unroll
    for (int it = tid; it < 512; it += 256) {     // A hi+lo
        int arr = it >> 8, idx = it & 255;
        int r = idx >> 2, q = idx & 3;
        const __nv_bfloat16* src = arr ? g_hlo : g_hhi;
        cpa16(sbuf + (arr ? G2_A_LO : G2_A_HI) + (uint32_t)(r * G2_AS + q * 8) * 2,
              (const char*)src + ((size_t)(row0 + r) * H2C + ch * 32 + q * 8) * 2);
    }
#pragma unroll
    for (int it = tid; it < 2048; it += 256) {    // B hi+lo: 32 x 256
        int arr = it >> 10, idx = it & 1023;
        int r = idx >> 5, c = idx & 31;
        const __nv_bfloat16* src = arr ? g_w2lo : g_w2hi;
        cpa16(sbuf + (arr ? G2_B_LO : G2_B_HI) + (uint32_t)(r * G2_BS + c * 8) * 2,
              (const char*)src + ((size_t)(ch * 32 + r) * H1C + c * 8) * 2);
    }
}

__global__ __launch_bounds__(256, 2) void gemm2_kernel(
    const float* __restrict__ b2, float* __restrict__ out)
{
    extern __shared__ char smem[];
    const uint32_t sb = smem_u32(smem);
    const int tid  = threadIdx.x;
    const int lane = tid & 31;
    const int wid  = tid >> 5;
    const int wm   = wid >> 2;        // 0..1
    const int wn   = wid & 3;         // 0..3
    const int row0 = blockIdx.x * 64;

    float* b2s = (float*)(smem + G2_B2S);
    for (int i = tid; i < H1C; i += 256) b2s[i] = b2[i];

    const int mi = lane >> 3, ri = lane & 7;
    const uint32_t aA = ((uint32_t)((wm * 32 + ri + ((mi & 1) << 3)) * G2_AS
                                    + ((mi >> 1) << 3))) * 2;
    const uint32_t aB = ((uint32_t)((ri + ((mi & 1) << 3)) * G2_BS
                                    + wn * 64 + ((mi >> 1) << 3))) * 2;

    float acc[2][8][4];
#pragma unroll
    for (int m = 0; m < 2; m++)
#pragma unroll
        for (int n = 0; n < 8; n++)
#pragma unroll
            for (int e = 0; e < 4; e++) acc[m][n][e] = 0.0f;

    g2_stage(sb, row0, 0, tid);
    cpa_commit();

    for (int ch = 0; ch < 16; ch++) {
        if (ch + 1 < 16) {
            g2_stage(sb + ((ch + 1) & 1) * G2_BUFSZ, row0, ch + 1, tid);
            cpa_commit();
            cpa_wait<1>();
        } else {
            cpa_wait<0>();
        }
        __syncthreads();

        const uint32_t base = sb + (ch & 1) * G2_BUFSZ;
#pragma unroll
        for (int ks = 0; ks < 2; ks++) {
            uint32_t ah[2][4], al[2][4];
#pragma unroll
            for (int ma = 0; ma < 2; ma++) {
                uint32_t off = aA + (ma * 16 * G2_AS + ks * 16) * 2;
                ldmx4(ah[ma], base + G2_A_HI + off);
                ldmx4(al[ma], base + G2_A_LO + off);
            }
#pragma unroll
            for (int pn = 0; pn < 4; pn++) {
                uint32_t bh[4], bl[4];
                uint32_t off = aB + (ks * 16 * G2_BS + pn * 16) * 2;
                ldmx4t(bh, base + G2_B_HI + off);
                ldmx4t(bl, base + G2_B_LO + off);
#pragma unroll
                for (int ma = 0; ma < 2; ma++) {
#pragma unroll
                    for (int nn = 0; nn < 2; nn++) {
                        float* d = acc[ma][pn * 2 + nn];
                        mma16816(d, ah[ma], bh[nn * 2], bh[nn * 2 + 1]);
                        mma16816(d, al[ma], bh[nn * 2], bh[nn * 2 + 1]);
                        mma16816(d, ah[ma], bl[nn * 2], bl[nn * 2 + 1]);
                    }
                }
            }
        }
        __syncthreads();
    }

    // ---- Epilogue: bias + store fp32 ----
#pragma unroll
    for (int ma = 0; ma < 2; ma++)
#pragma unroll
        for (int h = 0; h < 2; h++) {
            int row = wm * 32 + ma * 16 + h * 8 + (lane >> 2);
            float* op = out + (size_t)(row0 + row) * H1C;
#pragma unroll
            for (int na = 0; na < 8; na++) {
                int col = wn * 64 + na * 8 + (lane & 3) * 2;
                float2 v;
                v.x = acc[ma][na][h * 2]     + b2s[col];
                v.y = acc[ma][na][h * 2 + 1] + b2s[col + 1];
                *(float2*)(op + col) = v;
            }
        }
}

// ---------------------------------------------------------------------------
// Launch
// ---------------------------------------------------------------------------
extern "C" void kernel_launch(void* const* d_in, const int* in_sizes, int n_in,
                              void* d_out, int out_size) {
    const float* x   = (const float*)d_in[0];
    const float* w1  = (const float*)d_in[1];
    const float* b1  = (const float*)d_in[2];
    const float* lng = (const float*)d_in[3];
    const float* lnb = (const float*)d_in[4];
    const float* w2  = (const float*)d_in[5];
    const float* b2  = (const float*)d_in[6];
    float* out = (float*)d_out;

    cudaFuncSetAttribute(gemm1_kernel, cudaFuncAttributeMaxDynamicSharedMemorySize, SMEM_G1);
    cudaFuncSetAttribute(gemm2_kernel, cudaFuncAttributeMaxDynamicSharedMemorySize, SMEM_G2);

    prep_kernel<<<(KP1 * H2C + H2C * H1C + 255) / 256, 256>>>(w1, w2);
    sig_kernel<<<NTOT / NW, 256>>>(x);
    gemm1_kernel<<<NTOT / 64, 512, SMEM_G1>>>(b1, lng, lnb);
    gemm2_kernel<<<NTOT / 64, 256, SMEM_G2>>>(b2, out);
}

// round 15
// speedup vs baseline: 1.0393x; 1.0393x over previous
#include <cuda_runtime.h>
#include <cuda_bf16.h>
#include <math.h>
#include <stdint.h>

// Problem constants
#define BB     8
#define SS     2048
#define CC     8
#define DD     9
#define WIN    60
#define NTOT   (BB * SS)      // 16384
#define SIGCH  285
#define KP1    288            // padded K for GEMM1 (9 chunks of 32)
#define H2C    512
#define H1C    256
#define NW     8

// ---------------- scratch ----------------
__device__ __nv_bfloat16 g_fhi[(size_t)NTOT * KP1];
__device__ __nv_bfloat16 g_flo[(size_t)NTOT * KP1];
__device__ __nv_bfloat16 g_w1hi[KP1 * H2C];
__device__ __nv_bfloat16 g_w1lo[KP1 * H2C];
__device__ __nv_bfloat16 g_w2hi[H2C * H1C];
__device__ __nv_bfloat16 g_w2lo[H2C * H1C];

// ---------------- Lyndon tables ----------------
struct LyndonTab { short l2[36]; short l3[240]; };
constexpr LyndonTab make_tab() {
    LyndonTab t{};
    int n2 = 0, n3 = 0;
    for (int i = 0; i < DD; i++)
        for (int j = 0; j < DD; j++)
            if (i < j) t.l2[n2++] = (short)(i * 9 + j);
    for (int i = 0; i < DD; i++)
        for (int j = 0; j < DD; j++)
            for (int k = 0; k < DD; k++) {
                int e  = (i * 9 + j) * 9 + k;
                int r1 = (j * 9 + k) * 9 + i;
                int r2 = (k * 9 + i) * 9 + j;
                if (e < r1 && e < r2) t.l3[n3++] = (short)e;
            }
    return t;
}
__constant__ LyndonTab c_tab = make_tab();

// ---------------- helpers ----------------
__device__ __forceinline__ float gelu_exact(float v) {
    return 0.5f * v * (1.0f + erff(v * 0.70710678118654752f));
}
__device__ __forceinline__ void feat_store(int n, int idx, float v) {
    __nv_bfloat16 h = __float2bfloat16(v);
    g_fhi[(size_t)n * KP1 + idx] = h;
    g_flo[(size_t)n * KP1 + idx] = __float2bfloat16(v - __bfloat162float(h));
}
__device__ __forceinline__ uint32_t pkbf2(float a, float b) {
    __nv_bfloat162 t = __floats2bfloat162_rn(a, b);
    return *(uint32_t*)&t;
}
__device__ __forceinline__ uint32_t smem_u32(const void* p) {
    uint32_t a;
    asm("{ .reg .u64 t; cvta.to.shared.u64 t, %1; cvt.u32.u64 %0, t; }" : "=r"(a) : "l"(p));
    return a;
}
__device__ __forceinline__ void ldmx4(uint32_t* r, uint32_t addr) {
    asm volatile("ldmatrix.sync.aligned.m8n8.x4.shared.b16 {%0,%1,%2,%3}, [%4];"
                 : "=r"(r[0]), "=r"(r[1]), "=r"(r[2]), "=r"(r[3]) : "r"(addr));
}
__device__ __forceinline__ void ldmx4t(uint32_t* r, uint32_t addr) {
    asm volatile("ldmatrix.sync.aligned.m8n8.x4.trans.shared.b16 {%0,%1,%2,%3}, [%4];"
                 : "=r"(r[0]), "=r"(r[1]), "=r"(r[2]), "=r"(r[3]) : "r"(addr));
}
__device__ __forceinline__ void mma16816(float* d, const uint32_t* a,
                                         uint32_t b0, uint32_t b1) {
    asm volatile("mma.sync.aligned.m16n8k16.row.col.f32.bf16.bf16.f32 "
                 "{%0,%1,%2,%3}, {%4,%5,%6,%7}, {%8,%9}, {%0,%1,%2,%3};"
                 : "+f"(d[0]), "+f"(d[1]), "+f"(d[2]), "+f"(d[3])
                 : "r"(a[0]), "r"(a[1]), "r"(a[2]), "r"(a[3]), "r"(b0), "r"(b1));
}
__device__ __forceinline__ void cpa16(uint32_t dst, const void* src) {
    asm volatile("cp.async.cg.shared.global [%0], [%1], 16;" :: "r"(dst), "l"(src));
}
__device__ __forceinline__ void cpa_commit() {
    asm volatile("cp.async.commit_group;" ::: "memory");
}
template <int N>
__device__ __forceinline__ void cpa_wait() {
    asm volatile("cp.async.wait_group %0;" :: "n"(N) : "memory");
}
// ---- packed fp32x2 (FFMA2) ----
__device__ __forceinline__ unsigned long long pk2f(float lo, float hi) {
    unsigned long long r;
    asm("mov.b64 %0, {%1, %2};" : "=l"(r) : "f"(lo), "f"(hi));
    return r;
}
__device__ __forceinline__ void upk2f(unsigned long long v, float& lo, float& hi) {
    asm("mov.b64 {%0, %1}, %2;" : "=f"(lo), "=f"(hi) : "l"(v));
}
__device__ __forceinline__ void ffma2(unsigned long long& d, unsigned long long a,
                                      unsigned long long b) {
    asm("fma.rn.f32x2 %0, %1, %2, %0;" : "+l"(d) : "l"(a), "l"(b));
}

// ---------------------------------------------------------------------------
// Prep: bf16 hi/lo weights in natural [K][N] layout (K padded for w1).
// ---------------------------------------------------------------------------
__global__ void prep_kernel(const float* __restrict__ w1, const float* __restrict__ w2) {
    int idx = blockIdx.x * 256 + threadIdx.x;
    if (idx < KP1 * H2C) {
        int k = idx / H2C, n = idx - k * H2C;
        float v = (k < SIGCH) ? w1[(size_t)k * H2C + n] : 0.0f;
        __nv_bfloat16 h = __float2bfloat16(v);
        g_w1hi[idx] = h;
        g_w1lo[idx] = __float2bfloat16(v - __bfloat162float(h));
    } else {
        int j = idx - KP1 * H2C;
        if (j < H2C * H1C) {
            float v = w2[j];
            __nv_bfloat16 h = __float2bfloat16(v);
            g_w2hi[j] = h;
            g_w2lo[j] = __float2bfloat16(v - __bfloat162float(h));
        }
    }
}

// ---------------------------------------------------------------------------
// Kernel A: log-signature features (warp per window) -> bf16 hi/lo [n][288]
// ---------------------------------------------------------------------------
__global__ __launch_bounds__(256) void sig_kernel(const float* __restrict__ x) {
    __shared__ float vs3[NW][732];
    __shared__ float s2s[NW][81];
    __shared__ float s1s[NW][12];

    const int w    = threadIdx.x >> 5;
    const int lane = threadIdx.x & 31;
    const int n    = blockIdx.x * NW + w;
    const int bb   = n >> 11;
    const int ss   = n & 2047;

    float* vbuf = vs3[w];
    const float inv59 = 1.0f / 59.0f;

    for (int step = lane; step < WIN; step += 32) {
        int pos  = ss + step - (WIN - 1);
        int posc = pos < 0 ? 0 : pos;
        const float* xr = x + ((size_t)bb * SS + posc) * CC;
        float4 a0 = *(const float4*)(xr);
        float4 a1 = *(const float4*)(xr + 4);
        float vt;
        float4 d0, d1;
        if (step == 0) {
            vt = 0.0f;
            d0 = a0; d1 = a1;
        } else {
            vt = inv59;
            int pm  = pos - 1;
            int pmc = pm < 0 ? 0 : pm;
            const float* xp = x + ((size_t)bb * SS + pmc) * CC;
            float4 b0 = *(const float4*)(xp);
            float4 b1 = *(const float4*)(xp + 4);
            d0.x = a0.x - b0.x; d0.y = a0.y - b0.y; d0.z = a0.z - b0.z; d0.w = a0.w - b0.w;
            d1.x = a1.x - b1.x; d1.y = a1.y - b1.y; d1.z = a1.z - b1.z; d1.w = a1.w - b1.w;
        }
        float* vv = vbuf + step * 12;
        vv[0] = vt;
        vv[1] = d0.x; vv[2] = d0.y; vv[3] = d0.z; vv[4] = d0.w;
        vv[5] = d1.x; vv[6] = d1.y; vv[7] = d1.z; vv[8] = d1.w;
    }
    __syncwarp();

    unsigned long long S3p[3][5];
    float S2r[3];
    float s1i = 0.0f;
    const int li = lane / 3;
    const int jb = (lane % 3) * 3;

    if (lane < 27) {
#pragma unroll
        for (int c = 0; c < 3; c++) {
            S2r[c] = 0.0f;
#pragma unroll
            for (int q = 0; q < 5; q++) S3p[c][q] = 0ull;
        }
#pragma unroll 2
        for (int step = 0; step < WIN; step++) {
            const float* vv = vbuf + step * 12;
            float4 va = *(const float4*)(vv);
            float4 vb = *(const float4*)(vv + 4);
            float  v8 = vv[8];
            float  vi = vv[li];
            unsigned long long pv[5];
            pv[0] = pk2f(va.x, va.y);
            pv[1] = pk2f(va.z, va.w);
            pv[2] = pk2f(vb.x, vb.y);
            pv[3] = pk2f(vb.z, vb.w);
            pv[4] = pk2f(v8, 0.0f);
            float bcoef = fmaf(vi, 1.0f / 6.0f, 0.5f * s1i);
            float ccoef = fmaf(vi, 0.5f, s1i);
#pragma unroll
            for (int c = 0; c < 3; c++) {
                float vj = vv[jb + c];
                float a = fmaf(bcoef, vj, S2r[c]);
                unsigned long long pa = pk2f(a, a);
#pragma unroll
                for (int q = 0; q < 5; q++) ffma2(S3p[c][q], pv[q], pa);
                S2r[c] = fmaf(ccoef, vj, S2r[c]);
            }
            s1i += vi;
        }
    }
    __syncwarp();

    if (lane < 27) {
#pragma unroll
        for (int c = 0; c < 3; c++) {
            int p = li * 9 + jb + c;
            s2s[w][p] = S2r[c];
            float lo, hi;
#pragma unroll
            for (int q = 0; q < 4; q++) {
                upk2f(S3p[c][q], lo, hi);
                vs3[w][p * 9 + 2 * q]     = lo;
                vs3[w][p * 9 + 2 * q + 1] = hi;
            }
            upk2f(S3p[c][4], lo, hi);
            vs3[w][p * 9 + 8] = lo;
        }
        if ((lane % 3) == 0) s1s[w][li] = s1i;
    }
    __syncwarp();

    const float* S3s = vs3[w];
    const float* S2p = s2s[w];
    const float* S1p = s1s[w];

    if (lane < 9) feat_store(n, lane, S1p[lane]);

    for (int t = lane; t < 36; t += 32) {
        int e = c_tab.l2[t];
        int i = e / 9, j = e % 9;
        feat_store(n, 9 + t, S2p[e] - 0.5f * S1p[i] * S1p[j]);
    }
    for (int t = lane; t < 240; t += 32) {
        int e  = c_tab.l3[t];
        int k  = e % 9;
        int ij = e / 9;
        int j  = ij % 9;
        int i  = ij / 9;
        float v = S3s[e]
                - 0.5f * (S1p[i] * S2p[j * 9 + k] + S2p[ij] * S1p[k])
                + S1p[i] * S1p[j] * S1p[k] * (1.0f / 3.0f);
        feat_store(n, 45 + t, v);
    }
    for (int t = SIGCH + lane; t < KP1; t += 32) {
        g_fhi[(size_t)n * KP1 + t] = __float2bfloat16(0.0f);
        g_flo[(size_t)n * KP1 + t] = __float2bfloat16(0.0f);
    }
}

// ---------------------------------------------------------------------------
// FUSED MLP: phase1 (64x512 split-bf16 MMA + GELU + LN -> h in SMEM),
// phase2 (64x256 split-bf16 MMA from smem h, w2 streamed) -> out.
// 256 CTAs x 512 threads.
// ---------------------------------------------------------------------------
// Phase1 staging (temporal, reused later by h):
#define G1_AS    40
#define G1_BS    520
#define G1_A_HI  0
#define G1_A_LO  (G1_A_HI + 64 * G1_AS * 2)       // 5120
#define G1_B_HI  (G1_A_LO + 64 * G1_AS * 2)       // 10240
#define G1_B_LO  (G1_B_HI + 32 * G1_BS * 2)       // 43520
#define G1_BUFSZ (G1_B_LO + 32 * G1_BS * 2)       // 76800
// h tile (overlaps phase1 staging; valid after phase1 mainloop):
#define HSH      520                              // h smem stride in halves
#define F_H_HI   0
#define F_H_LO   (64 * HSH * 2)                   // 66560 ; end 133120
// w2 double buffers (disjoint from everything above):
#define W2_HI    0
#define W2_LO    16896                            // within a w2 buffer
#define W2_BUFSZ 33792
#define F_W2     153600                           // two bufs: end 221184
// aux:
#define F_B1S    221184                           // 512 f (b2s overlaid later)
#define F_LNG    (F_B1S + 2048)
#define F_LNB    (F_LNG + 2048)
#define F_RS     (F_LNB + 2048)                   // 64x8 f
#define F_RQ     (F_RS + 2048)
#define F_MU     (F_RQ + 2048)                    // 64 f
#define F_RSD    (F_MU + 256)
#define SMEM_F   (F_RSD + 256)                    // 231936

__device__ __forceinline__ void g1_stage(uint32_t sbuf, int row0, int ch, int tid) {
    {
        int arr = tid >> 8, idx = tid & 255;
        int r = idx >> 2, q = idx & 3;
        const __nv_bfloat16* src = arr ? g_flo : g_fhi;
        cpa16(sbuf + (arr ? G1_A_LO : G1_A_HI) + (uint32_t)(r * G1_AS + q * 8) * 2,
              (const char*)src + ((size_t)(row0 + r) * KP1 + ch * 32 + q * 8) * 2);
    }
#pragma unroll
    for (int it = tid; it < 4096; it += 512) {
        int arr = it >> 11, idx = it & 2047;
        int r = idx >> 6, c = idx & 63;
        const __nv_bfloat16* src = arr ? g_w1lo : g_w1hi;
        cpa16(sbuf + (arr ? G1_B_LO : G1_B_HI) + (uint32_t)(r * G1_BS + c * 8) * 2,
              (const char*)src + ((size_t)(ch * 32 + r) * H2C + c * 8) * 2);
    }
}

__device__ __forceinline__ void w2_stage(uint32_t sbuf, int ch, int tid) {
#pragma unroll
    for (int it = tid; it < 2048; it += 512) {
        int arr = it >> 10, idx = it & 1023;
        int r = idx >> 5, c = idx & 31;
        const __nv_bfloat16* src = arr ? g_w2lo : g_w2hi;
        cpa16(sbuf + (arr ? W2_LO : W2_HI) + (uint32_t)(r * 264 + c * 8) * 2,
              (const char*)src + ((size_t)(ch * 32 + r) * H1C + c * 8) * 2);
    }
}

__global__ __launch_bounds__(512, 1) void mlp_fused_kernel(
    const float* __restrict__ b1, const float* __restrict__ lng,
    const float* __restrict__ lnb, const float* __restrict__ b2,
    float* __restrict__ out)
{
    extern __shared__ char smem[];
    const uint32_t sb = smem_u32(smem);
    const int tid  = threadIdx.x;
    const int lane = tid & 31;
    const int wid  = tid >> 5;
    const int wm   = wid >> 3;        // 0..1
    const int wn   = wid & 7;         // 0..7
    const int row0 = blockIdx.x * 64;

    float* b1s  = (float*)(smem + F_B1S);
    float* lngs = (float*)(smem + F_LNG);
    float* lnbs = (float*)(smem + F_LNB);
    float* reds = (float*)(smem + F_RS);
    float* redq = (float*)(smem + F_RQ);
    float* mus  = (float*)(smem + F_MU);
    float* rsd  = (float*)(smem + F_RSD);
    for (int i = tid; i < H2C; i += 512) {
        b1s[i] = b1[i]; lngs[i] = lng[i]; lnbs[i] = lnb[i];
    }

    const int mi = lane >> 3, ri = lane & 7;
    const uint32_t aA = ((uint32_t)((wm * 32 + ri + ((mi & 1) << 3)) * G1_AS
                                    + ((mi >> 1) << 3))) * 2;
    const uint32_t aB = ((uint32_t)((ri + ((mi & 1) << 3)) * G1_BS
                                    + wn * 64 + ((mi >> 1) << 3))) * 2;

    float acc[2][8][4];
#pragma unroll
    for (int m = 0; m < 2; m++)
#pragma unroll
        for (int n = 0; n < 8; n++)
#pragma unroll
            for (int e = 0; e < 4; e++) acc[m][n][e] = 0.0f;

    // ================= PHASE 1: feats @ w1 =================
    g1_stage(sb, row0, 0, tid);
    cpa_commit();

    for (int ch = 0; ch < 9; ch++) {
        if (ch + 1 < 9) {
            g1_stage(sb + ((ch + 1) & 1) * G1_BUFSZ, row0, ch + 1, tid);
            cpa_commit();
            cpa_wait<1>();
        } else {
            cpa_wait<0>();
        }
        __syncthreads();

        const uint32_t base = sb + (ch & 1) * G1_BUFSZ;
#pragma unroll
        for (int ks = 0; ks < 2; ks++) {
            uint32_t ah[2][4], al[2][4];
#pragma unroll
            for (int ma = 0; ma < 2; ma++) {
                uint32_t off = aA + (ma * 16 * G1_AS + ks * 16) * 2;
                ldmx4(ah[ma], base + G1_A_HI + off);
                ldmx4(al[ma], base + G1_A_LO + off);
            }
#pragma unroll
            for (int pn = 0; pn < 4; pn++) {
                uint32_t bh[4], bl[4];
                uint32_t off = aB + (ks * 16 * G1_BS + pn * 16) * 2;
                ldmx4t(bh, base + G1_B_HI + off);
                ldmx4t(bl, base + G1_B_LO + off);
#pragma unroll
                for (int ma = 0; ma < 2; ma++) {
#pragma unroll
                    for (int nn = 0; nn < 2; nn++) {
                        float* d = acc[ma][pn * 2 + nn];
                        mma16816(d, ah[ma], bh[nn * 2], bh[nn * 2 + 1]);
                        mma16816(d, al[ma], bh[nn * 2], bh[nn * 2 + 1]);
                        mma16816(d, ah[ma], bl[nn * 2], bl[nn * 2 + 1]);
                    }
                }
            }
        }
        __syncthreads();
    }

    // Prefetch w2 chunk 0 now; latency hides under the LN epilogue.
    w2_stage(sb + F_W2, 0, tid);
    cpa_commit();

    // ---- GELU + LN stats ----
    float s1v[2][2] = {{0.f, 0.f}, {0.f, 0.f}};
    float s2v[2][2] = {{0.f, 0.f}, {0.f, 0.f}};
#pragma unroll
    for (int ma = 0; ma < 2; ma++)
#pragma unroll
        for (int na = 0; na < 8; na++) {
            int col = wn * 64 + na * 8 + (lane & 3) * 2;
#pragma unroll
            for (int e = 0; e < 4; e++) {
                float v = gelu_exact(acc[ma][na][e] + b1s[col + (e & 1)]);
                acc[ma][na][e] = v;
                s1v[ma][e >> 1] += v;
                s2v[ma][e >> 1] = fmaf(v, v, s2v[ma][e >> 1]);
            }
        }
#pragma unroll
    for (int off = 1; off <= 2; off <<= 1) {
#pragma unroll
        for (int ma = 0; ma < 2; ma++)
#pragma unroll
            for (int h = 0; h < 2; h++) {
                s1v[ma][h] += __shfl_xor_sync(0xffffffffu, s1v[ma][h], off);
                s2v[ma][h] += __shfl_xor_sync(0xffffffffu, s2v[ma][h], off);
            }
    }
    if ((lane & 3) == 0) {
#pragma unroll
        for (int ma = 0; ma < 2; ma++)
#pragma unroll
            for (int h = 0; h < 2; h++) {
                int row = wm * 32 + ma * 16 + h * 8 + (lane >> 2);
                reds[row * 8 + wn] = s1v[ma][h];
                redq[row * 8 + wn] = s2v[ma][h];
            }
    }
    __syncthreads();
    // b1s is dead now -> overlay b2s into the same region.
    float* b2s = b1s;
    for (int i = tid; i < H1C; i += 512) b2s[i] = b2[i];
    if (tid < 64) {
        float s = 0.f, q = 0.f;
#pragma unroll
        for (int w = 0; w < 8; w++) { s += reds[tid * 8 + w]; q += redq[tid * 8 + w]; }
        float mu  = s * (1.0f / 512.0f);
        float var = q * (1.0f / 512.0f) - mu * mu;
        mus[tid] = mu;
        rsd[tid] = rsqrtf(var + 1e-5f);
    }
    __syncthreads();

    // ---- Normalize, write h into SMEM (bf16 hi/lo) ----
#pragma unroll
    for (int ma = 0; ma < 2; ma++)
#pragma unroll
        for (int h = 0; h < 2; h++) {
            int row = wm * 32 + ma * 16 + h * 8 + (lane >> 2);
            float mu = mus[row], rs = rsd[row];
#pragma unroll
            for (int na = 0; na < 8; na++) {
                int col = wn * 64 + na * 8 + (lane & 3) * 2;
                float y0 = fmaf((acc[ma][na][h * 2]     - mu) * rs, lngs[col],     lnbs[col]);
                float y1 = fmaf((acc[ma][na][h * 2 + 1] - mu) * rs, lngs[col + 1], lnbs[col + 1]);
                __nv_bfloat16 h0 = __float2bfloat16(y0), h1 = __float2bfloat16(y1);
                float f0 = __bfloat162float(h0), f1 = __bfloat162float(h1);
                uint32_t off = (uint32_t)(row * HSH + col) * 2;
                *(uint32_t*)(smem + F_H_HI + off) = pkbf2(f0, f1);
                *(uint32_t*)(smem + F_H_LO + off) = pkbf2(y0 - f0, y1 - f1);
            }
        }
    __syncthreads();

    // ================= PHASE 2: h @ w2 =================
    // 16 warps, output 64x256: warp tile 32x32 (wm x wn reused: wn*32 cols).
    float ac2[2][4][4];
#pragma unroll
    for (int m = 0; m < 2; m++)
#pragma unroll
        for (int n = 0; n < 4; n++)
#pragma unroll
            for (int e = 0; e < 4; e++) ac2[m][n][e] = 0.0f;

    const uint32_t aB2 = ((uint32_t)((ri + ((mi & 1) << 3)) * 264
                                     + wn * 32 + ((mi >> 1) << 3))) * 2;
    const uint32_t aA2row = (uint32_t)(wm * 32 + ri + ((mi & 1) << 3));
    const uint32_t aA2col = (uint32_t)((mi >> 1) << 3);

    for (int ch = 0; ch < 16; ch++) {
        if (ch + 1 < 16) {
            w2_stage(sb + F_W2 + ((ch + 1) & 1) * W2_BUFSZ, ch + 1, tid);
            cpa_commit();
            cpa_wait<1>();
        } else {
            cpa_wait<0>();
        }
        __syncthreads();

        const uint32_t wb = sb + F_W2 + (ch & 1) * W2_BUFSZ;
#pragma unroll
        for (int ks = 0; ks < 2; ks++) {
            uint32_t ah[2][4], al[2][4];
#pragma unroll
            for (int ma = 0; ma < 2; ma++) {
                uint32_t off = ((aA2row + ma * 16) * HSH
                                + ch * 32 + ks * 16 + aA2col) * 2;
                ldmx4(ah[ma], sb + F_H_HI + off);
                ldmx4(al[ma], sb + F_H_LO + off);
            }
#pragma unroll
            for (int pn = 0; pn < 2; pn++) {
                uint32_t bh[4], bl[4];
                uint32_t off = aB2 + (ks * 16 * 264 + pn * 16) * 2;
                ldmx4t(bh, wb + W2_HI + off);
                ldmx4t(bl, wb + W2_LO + off);
#pragma unroll
                for (int ma = 0; ma < 2; ma++) {
#pragma unroll
                    for (int nn = 0; nn < 2; nn++) {
                        float* d = ac2[ma][pn * 2 + nn];
                        mma16816(d, ah[ma], bh[nn * 2], bh[nn * 2 + 1]);
                        mma16816(d, al[ma], bh[nn * 2], bh[nn * 2 + 1]);
                        mma16816(d, ah[ma], bl[nn * 2], bl[nn * 2 + 1]);
                    }
                }
            }
        }
        __syncthreads();
    }

    // ---- Phase2 epilogue: bias + store fp32 ----
#pragma unroll
    for (int ma = 0; ma < 2; ma++)
#pragma unroll
        for (int h = 0; h < 2; h++) {
            int row = wm * 32 + ma * 16 + h * 8 + (lane >> 2);
            float* op = out + (size_t)(row0 + row) * H1C;
#pragma unroll
            for (int na = 0; na < 4; na++) {
                int col = wn * 32 + na * 8 + (lane & 3) * 2;
                float2 v;
                v.x = ac2[ma][na][h * 2]     + b2s[col];
                v.y = ac2[ma][na][h * 2 + 1] + b2s[col + 1];
                *(float2*)(op + col) = v;
            }
        }
}

// ---------------------------------------------------------------------------
// Launch
// ---------------------------------------------------------------------------
extern "C" void kernel_launch(void* const* d_in, const int* in_sizes, int n_in,
                              void* d_out, int out_size) {
    const float* x   = (const float*)d_in[0];
    const float* w1  = (const float*)d_in[1];
    const float* b1  = (const float*)d_in[2];
    const float* lng = (const float*)d_in[3];
    const float* lnb = (const float*)d_in[4];
    const float* w2  = (const float*)d_in[5];
    const float* b2  = (const float*)d_in[6];
    float* out = (float*)d_out;

    cudaFuncSetAttribute(mlp_fused_kernel,
                         cudaFuncAttributeMaxDynamicSharedMemorySize, SMEM_F);

    prep_kernel<<<(KP1 * H2C + H2C * H1C + 255) / 256, 256>>>(w1, w2);
    sig_kernel<<<NTOT / NW, 256>>>(x);
    mlp_fused_kernel<<<NTOT / 64, 512, SMEM_F>>>(b1, lng, lnb, b2, out);
}